// round 17
// baseline (speedup 1.0000x reference)
#include <cuda_runtime.h>
#include <cstdint>

// Problem constants (fixed by the reference: B=64, S=512, H=768)
#define PB 64
#define PS 512
#define PH 768
#define NTOK (PB * PS)                       // 32768 tokens
#define SPAN ((size_t)PB * PS * PS)          // 16,777,216 elements per output tensor

// Per-token scratch (device globals: allocation-free, graph-capturable)
__device__ float         g_a[NTOK];
__device__ float         g_c[NTOK];
__device__ unsigned char g_sc[NTOK];
__device__ unsigned char g_ec[NTOK];

// ---------------------------------------------------------------------------
// Kernel 1 (R11/R12 verbatim, measured 25.7us): per-token fused matvecs,
// 4 tokens/warp + software-pipelined rep loads (8 LDG.128 in flight/warp).
// Weight LDS shared across 4 tokens; merged 6-shuffle reduction.
// NOTE: no occupancy pragma -- capping to 5 blocks/SM spills the prefetch
// buffer to local memory (R15: token 25.7 -> 36.8us).
// ---------------------------------------------------------------------------
__global__ void __launch_bounds__(256) void_guard();  // (decl quirk guard)

__global__ void __launch_bounds__(256) token_kernel(
    const float* __restrict__ rep,
    const int*   __restrict__ mask,
    const float* __restrict__ W_start,
    const float* __restrict__ b_start,
    const float* __restrict__ W_end,
    const float* __restrict__ b_end,
    const float* __restrict__ W_m,
    const float* __restrict__ b_m)
{
    __shared__ float4 sw[4][PH / 4];   // 12 KB: 4 combined weight vectors

    const int tid = threadIdx.x;

    // Stage combined weights into shared (once per block)
    for (int i = tid; i < PH; i += blockDim.x) {
        reinterpret_cast<float*>(sw[0])[i] = W_start[i * 2 + 1] - W_start[i * 2 + 0];
        reinterpret_cast<float*>(sw[1])[i] = W_end[i * 2 + 1]   - W_end[i * 2 + 0];
        reinterpret_cast<float*>(sw[2])[i] = W_m[i];
        reinterpret_cast<float*>(sw[3])[i] = W_m[PH + i];
    }
    __syncthreads();

    const int warp = tid >> 5;
    const int lane = tid & 31;
    const int t0   = (blockIdx.x * 8 + warp) * 4;     // 4 consecutive tokens

    const float bsd = b_start[1] - b_start[0];
    const float bed = b_end[1]   - b_end[0];
    const float bm  = b_m[0];

    const float4* r4 = reinterpret_cast<const float4*>(rep) + (size_t)t0 * (PH / 4);

    float accd[4] = {0.f, 0.f, 0.f, 0.f};
    float acce[4] = {0.f, 0.f, 0.f, 0.f};
    float acca[4] = {0.f, 0.f, 0.f, 0.f};
    float accc[4] = {0.f, 0.f, 0.f, 0.f};

    // Prime the pipeline: iteration 0's loads.
    float4 x[4];
    #pragma unroll
    for (int j = 0; j < 4; ++j) x[j] = r4[(size_t)j * (PH / 4) + lane];

    #pragma unroll 1
    for (int k = 0; k < PH / 4 / 32; ++k) {           // 6 iterations, rolled
        const int i = lane + k * 32;

        // Prefetch next iteration's rep data before consuming this one's.
        float4 xn[4];
        if (k < PH / 4 / 32 - 1) {
            #pragma unroll
            for (int j = 0; j < 4; ++j) xn[j] = r4[(size_t)j * (PH / 4) + i + 32];
        }

        const float4 w0 = sw[0][i];
        const float4 w1 = sw[1][i];
        const float4 w2 = sw[2][i];
        const float4 w3 = sw[3][i];
        #pragma unroll
        for (int j = 0; j < 4; ++j) {
            accd[j] += x[j].x * w0.x + x[j].y * w0.y + x[j].z * w0.z + x[j].w * w0.w;
            acce[j] += x[j].x * w1.x + x[j].y * w1.y + x[j].z * w1.z + x[j].w * w1.w;
            acca[j] += x[j].x * w2.x + x[j].y * w2.y + x[j].z * w2.z + x[j].w * w2.w;
            accc[j] += x[j].x * w3.x + x[j].y * w3.y + x[j].z * w3.z + x[j].w * w3.w;
        }
        #pragma unroll
        for (int j = 0; j < 4; ++j) x[j] = xn[j];
    }

    // Merged reduction: 6 shuffles per token; lane%4 -> {d,e,a,c}.
    const unsigned full = 0xFFFFFFFFu;
    #pragma unroll
    for (int j = 0; j < 4; ++j) {
        const float t01 = (lane & 1) ? accd[j] : acce[j];
        const float m01 = ((lane & 1) ? acce[j] : accd[j]) + __shfl_xor_sync(full, t01, 1);
        const float t23 = (lane & 1) ? acca[j] : accc[j];
        const float m23 = ((lane & 1) ? accc[j] : acca[j]) + __shfl_xor_sync(full, t23, 1);
        const float tm  = (lane & 2) ? m01 : m23;
        float z = ((lane & 2) ? m23 : m01) + __shfl_xor_sync(full, tm, 2);
        z += __shfl_xor_sync(full, z, 4);
        z += __shfl_xor_sync(full, z, 8);
        z += __shfl_xor_sync(full, z, 16);

        const int tj = t0 + j;
        if (lane == 0) g_sc[tj] = (unsigned char)((mask[tj] != 0) && (z + bsd >= 0.f));
        if (lane == 1) g_ec[tj] = (unsigned char)((mask[tj] != 0) && (z + bed >= 0.f));
        if (lane == 2) g_a[tj]  = z + bm;
        if (lane == 3) g_c[tj]  = z;
    }
}

// ---------------------------------------------------------------------------
// 256-bit streaming store (sm_100 Blackwell: st.global.v8.f32, PTX >= 8.7).
// Halves the STG instruction/wavefront count vs 2x STG.128 -- span_kernel is
// L1-wavefront bound (L1 ~66% SOL, DRAM 41%), so fewer wavefronts = faster.
// ---------------------------------------------------------------------------
__device__ __forceinline__ void stg256_cs(float* p, const float4 a, const float4 b)
{
    asm volatile(
        "st.global.cs.v8.f32 [%0], {%1,%2,%3,%4,%5,%6,%7,%8};"
        :: "l"(p),
           "f"(a.x), "f"(a.y), "f"(a.z), "f"(a.w),
           "f"(b.x), "f"(b.y), "f"(b.z), "f"(b.w)
        : "memory");
}

// ---------------------------------------------------------------------------
// Kernel 2: span materialization with 8-wide e-slices + 256-bit stores.
// One block per (b, 16-row tile); 256 threads = 4 row-lanes x 64 e-slices
// (8 floats, 32B-aligned). Each thread register-caches its 8 c-values +
// 8 ec flags, reused across the 16 s-rows; per row it emits ONE v8 store
// for mask and ONE for scores.
//   scores[b,s,e] = a[b,s] + c[b,e]
//   mask = start_cand[b,s] & end_cand[b,e] & (s<=e) & (score>0)
// ---------------------------------------------------------------------------
#define ROWS_PER_BLK 16
__global__ void __launch_bounds__(256) span_kernel(float* __restrict__ out)
{
    const int b    = blockIdx.x >> 5;                 // / (S/ROWS_PER_BLK) = /32
    const int s0   = (blockIdx.x & 31) * ROWS_PER_BLK;
    const int rlan = threadIdx.x >> 6;                // 0..3: row lane
    const int e0   = (threadIdx.x & 63) << 3;         // fixed 8-wide e-slice

    const float4 cA = *reinterpret_cast<const float4*>(g_c + (b << 9) + e0);
    const float4 cB = *reinterpret_cast<const float4*>(g_c + (b << 9) + e0 + 4);
    const unsigned ecw0 = *reinterpret_cast<const unsigned*>(g_ec + (b << 9) + e0);
    const unsigned ecw1 = *reinterpret_cast<const unsigned*>(g_ec + (b << 9) + e0 + 4);
    const float ec0 = (ecw0 & 0x000000FFu) ? 1.f : 0.f;
    const float ec1 = (ecw0 & 0x0000FF00u) ? 1.f : 0.f;
    const float ec2 = (ecw0 & 0x00FF0000u) ? 1.f : 0.f;
    const float ec3 = (ecw0 & 0xFF000000u) ? 1.f : 0.f;
    const float ec4 = (ecw1 & 0x000000FFu) ? 1.f : 0.f;
    const float ec5 = (ecw1 & 0x0000FF00u) ? 1.f : 0.f;
    const float ec6 = (ecw1 & 0x00FF0000u) ? 1.f : 0.f;
    const float ec7 = (ecw1 & 0xFF000000u) ? 1.f : 0.f;

    #pragma unroll
    for (int r = rlan; r < ROWS_PER_BLK; r += 4) {
        const int s  = s0 + r;
        const int bs = (b << 9) + s;
        const float a  = g_a[bs];
        const float sc = g_sc[bs] ? 1.f : 0.f;

        float4 svA, svB;
        svA.x = a + cA.x;  svA.y = a + cA.y;  svA.z = a + cA.z;  svA.w = a + cA.w;
        svB.x = a + cB.x;  svB.y = a + cB.y;  svB.z = a + cB.z;  svB.w = a + cB.w;

        float4 mvA, mvB;
        mvA.x = (e0 + 0 >= s && svA.x > 0.f) ? sc * ec0 : 0.f;
        mvA.y = (e0 + 1 >= s && svA.y > 0.f) ? sc * ec1 : 0.f;
        mvA.z = (e0 + 2 >= s && svA.z > 0.f) ? sc * ec2 : 0.f;
        mvA.w = (e0 + 3 >= s && svA.w > 0.f) ? sc * ec3 : 0.f;
        mvB.x = (e0 + 4 >= s && svB.x > 0.f) ? sc * ec4 : 0.f;
        mvB.y = (e0 + 5 >= s && svB.y > 0.f) ? sc * ec5 : 0.f;
        mvB.z = (e0 + 6 >= s && svB.z > 0.f) ? sc * ec6 : 0.f;
        mvB.w = (e0 + 7 >= s && svB.w > 0.f) ? sc * ec7 : 0.f;

        const size_t off = (size_t)bs * PS + e0;
        stg256_cs(out + off,        mvA, mvB);   // span_mask
        stg256_cs(out + SPAN + off, svA, svB);   // scores
    }
}

// ---------------------------------------------------------------------------
extern "C" void kernel_launch(void* const* d_in, const int* in_sizes, int n_in,
                              void* d_out, int out_size)
{
    const float* rep     = (const float*)d_in[0];   // [B,S,H] fp32
    const int*   mask    = (const int*)  d_in[1];   // [B,S]  int32
    const float* W_start = (const float*)d_in[2];   // [H,2]
    const float* b_start = (const float*)d_in[3];   // [2]
    const float* W_end   = (const float*)d_in[4];   // [H,2]
    const float* b_end   = (const float*)d_in[5];   // [2]
    const float* W_m     = (const float*)d_in[6];   // [2H]
    const float* b_m     = (const float*)d_in[7];   // scalar
    float* out = (float*)d_out;                     // [mask | scores], each B*S*S fp32

    // Kernel 1: 8 warps x 4 tokens = 32 tokens per block -> 1024 blocks
    token_kernel<<<NTOK / 32, 256>>>(rep, mask, W_start, b_start, W_end, b_end, W_m, b_m);

    // Kernel 2: 64 batches x 32 row-tiles = 2048 blocks x 256 threads
    span_kernel<<<PB * (PS / ROWS_PER_BLK), 256>>>(out);
}

// Definition for the forward-declared guard (never launched).
__global__ void __launch_bounds__(256) void_guard() {}